// round 3
// baseline (speedup 1.0000x reference)
#include <cuda_runtime.h>
#include <cstdint>

#define NSUP 131072
#define DD   512
#define CC   1024
#define LL   3
#define ROWS 64
#define KB   32
#define NCHUNK (DD / KB)

// ---------------- device scratch (static: no runtime allocation) ----------------
__device__ float g_Xs[(size_t)NSUP * DD];   // label-sorted copy of support_features
__device__ int   g_cls[NSUP];               // class of each sorted row
__device__ int   g_counts[CC];
__device__ int   g_cursor[CC];
__device__ int   g_off[CC];
__device__ float g_S[LL * CC * DD];         // per-level class sums of g = relu(LN(X@W1+b1))

// ---------------- helpers ----------------
__device__ __forceinline__ void cp_async16(void* sdst, const void* gsrc) {
    unsigned s = (unsigned)__cvta_generic_to_shared(sdst);
    asm volatile("cp.async.cg.shared.global [%0], [%1], 16;" :: "r"(s), "l"(gsrc));
}
__device__ __forceinline__ void cp_commit() { asm volatile("cp.async.commit_group;"); }
__device__ __forceinline__ void cp_wait1()  { asm volatile("cp.async.wait_group 1;"); }
__device__ __forceinline__ void cp_wait0()  { asm volatile("cp.async.wait_group 0;"); }

__device__ __forceinline__ unsigned long long fma2(unsigned long long a,
                                                   unsigned long long b,
                                                   unsigned long long c) {
    unsigned long long d;
    asm("fma.rn.f32x2 %0, %1, %2, %3;" : "=l"(d) : "l"(a), "l"(b), "l"(c));
    return d;
}
__device__ __forceinline__ unsigned long long pack2(float x, float y) {
    unsigned long long d;
    asm("mov.b64 %0, {%1, %2};" : "=l"(d) : "f"(x), "f"(y));
    return d;
}
__device__ __forceinline__ float2 unpack2(unsigned long long v) {
    float2 f;
    asm("mov.b64 {%0, %1}, %2;" : "=f"(f.x), "=f"(f.y) : "l"(v));
    return f;
}

// ---------------- small kernels ----------------
__global__ void zero_kernel() {
    int i = blockIdx.x * 256 + threadIdx.x;
    if (i < LL * CC * DD) g_S[i] = 0.f;
    if (i < CC) { g_counts[i] = 0; g_cursor[i] = 0; }
}

__global__ void hist_kernel(const int* __restrict__ labels) {
    int i = blockIdx.x * 256 + threadIdx.x;
    if (i < NSUP) atomicAdd(&g_counts[labels[i]], 1);
}

__global__ void scan_kernel() {
    __shared__ int tmp[CC];
    int t = threadIdx.x;
    int v = g_counts[t];
    tmp[t] = v;
    __syncthreads();
    for (int o = 1; o < CC; o <<= 1) {
        int add = (t >= o) ? tmp[t - o] : 0;
        __syncthreads();
        tmp[t] += add;
        __syncthreads();
    }
    g_off[t] = tmp[t] - v;  // exclusive prefix
}

// one warp per row: stable-ish scatter of X rows into class-sorted order
__global__ void scatter_kernel(const float* __restrict__ X, const int* __restrict__ labels) {
    int row  = blockIdx.x * 8 + (threadIdx.x >> 5);
    int lane = threadIdx.x & 31;
    int c = labels[row];
    int pos = 0;
    if (lane == 0) pos = g_off[c] + atomicAdd(&g_cursor[c], 1);
    pos = __shfl_sync(0xffffffffu, pos, 0);
    if (lane == 0) g_cls[pos] = c;
    const float4* src = (const float4*)(X + (size_t)row * DD);
    float4* dst = (float4*)(g_Xs + (size_t)pos * DD);
#pragma unroll
    for (int i = 0; i < 4; i++) dst[lane + 32 * i] = src[lane + 32 * i];
}

// ---------------- main fused kernel ----------------
// Per CTA: 64 sorted rows x full D=512. GEMM (X@W1) with f32x2 FMAs,
// +b1, LayerNorm, ReLU, class-segment reduce, atomic into g_S[level].
// smem: As[2][64][32] (4096 f) | Bs[2][32][512] (32768 f, reused as H[64][512])
//       | gamma[512] beta[512] b1[512] | cls[64]
#define LVL_SMEM_BYTES (size_t)((4096 + 32768 + 1536) * 4 + 64 * 4)

__global__ __launch_bounds__(512, 1)
void level_kernel(const float* __restrict__ W1, const float* __restrict__ b1,
                  const float* __restrict__ gamma, const float* __restrict__ beta)
{
    extern __shared__ float sm[];
    float* As  = sm;                   // [2][64][32] row-major [row][k]
    float* Bs  = sm + 4096;            // [2][32][512] row-major [k][col]
    float* H   = Bs;                   // overlay after GEMM: [64][512]
    float* gms = sm + 4096 + 32768;
    float* bts = gms + 512;
    float* b1s = bts + 512;
    int*   clss = (int*)(b1s + 512);

    const int l = blockIdx.y;
    const int row0 = blockIdx.x * ROWS;
    const int tid = threadIdx.x;
    const float* W = W1 + (size_t)l * DD * DD;
    float* Sl = g_S + (size_t)l * CC * DD;

    gms[tid] = gamma[l * DD + tid];
    bts[tid] = beta[l * DD + tid];
    b1s[tid] = b1[l * DD + tid];
    if (tid < ROWS) clss[tid] = g_cls[row0 + tid];

    const int c_t = tid & 63;   // 64 col-groups x 8 cols (4 + 4 at +256)
    const int r_t = tid >> 6;   // 8 row-groups x 8 rows
    const int arow = tid >> 3, akk = (tid & 7) << 2;

    // prologue: chunk 0
    cp_async16(&As[arow * 32 + akk], &g_Xs[(size_t)(row0 + arow) * DD + akk]);
#pragma unroll
    for (int i = 0; i < 8; i++) {
        int idx = tid + i * 512;
        int k = idx >> 7, c4 = (idx & 127) << 2;
        cp_async16(&Bs[k * 512 + c4], &W[(size_t)k * DD + c4]);
    }
    cp_commit();

    unsigned long long acc[8][4];
#pragma unroll
    for (int i = 0; i < 8; i++)
#pragma unroll
        for (int j = 0; j < 4; j++) acc[i][j] = 0ULL;

    for (int ch = 0; ch < NCHUNK; ch++) {
        const int nb = ch & 1;
        if (ch + 1 < NCHUNK) {
            const int k0 = (ch + 1) * KB;
            const int dbuf = nb ^ 1;
            cp_async16(&As[dbuf * 2048 + arow * 32 + akk],
                       &g_Xs[(size_t)(row0 + arow) * DD + k0 + akk]);
#pragma unroll
            for (int i = 0; i < 8; i++) {
                int idx = tid + i * 512;
                int k = idx >> 7, c4 = (idx & 127) << 2;
                cp_async16(&Bs[dbuf * 16384 + k * 512 + c4], &W[(size_t)(k0 + k) * DD + c4]);
            }
            cp_commit();
            cp_wait1();
        } else {
            cp_wait0();
        }
        __syncthreads();

        const float* Ab = As + nb * 2048;
        const float* Bb = Bs + nb * 16384;
#pragma unroll 8
        for (int k = 0; k < KB; k++) {
            ulonglong2 bA = *(const ulonglong2*)(Bb + k * 512 + (c_t << 2));
            ulonglong2 bB = *(const ulonglong2*)(Bb + k * 512 + 256 + (c_t << 2));
#pragma unroll
            for (int i = 0; i < 8; i++) {
                float a = Ab[(r_t * 8 + i) * 32 + k];
                unsigned long long ap = pack2(a, a);
                acc[i][0] = fma2(ap, bA.x, acc[i][0]);
                acc[i][1] = fma2(ap, bA.y, acc[i][1]);
                acc[i][2] = fma2(ap, bB.x, acc[i][2]);
                acc[i][3] = fma2(ap, bB.y, acc[i][3]);
            }
        }
        __syncthreads();
    }

    // ---- epilogue: H = acc + b1 (overlay Bs) ----
    const int c0 = c_t << 2;
#pragma unroll
    for (int i = 0; i < 8; i++) {
        int row = r_t * 8 + i;
        float2 p0 = unpack2(acc[i][0]), p1 = unpack2(acc[i][1]);
        float2 p2 = unpack2(acc[i][2]), p3 = unpack2(acc[i][3]);
        float4 v0, v1;
        v0.x = p0.x + b1s[c0];         v0.y = p0.y + b1s[c0 + 1];
        v0.z = p1.x + b1s[c0 + 2];     v0.w = p1.y + b1s[c0 + 3];
        v1.x = p2.x + b1s[256 + c0];   v1.y = p2.y + b1s[256 + c0 + 1];
        v1.z = p3.x + b1s[256 + c0 + 2]; v1.w = p3.y + b1s[256 + c0 + 3];
        *(float4*)(H + row * 512 + c0) = v0;
        *(float4*)(H + row * 512 + 256 + c0) = v1;
    }
    __syncthreads();

    // ---- LayerNorm + ReLU: warp w handles rows 4w..4w+3 ----
    const int warp = tid >> 5, lane = tid & 31;
#pragma unroll
    for (int rr = 0; rr < 4; rr++) {
        int row = warp * 4 + rr;
        float s = 0.f, s2 = 0.f;
#pragma unroll
        for (int j = 0; j < 16; j++) {
            float v = H[row * 512 + lane + j * 32];
            s += v; s2 += v * v;
        }
#pragma unroll
        for (int o = 16; o; o >>= 1) {
            s  += __shfl_xor_sync(0xffffffffu, s, o);
            s2 += __shfl_xor_sync(0xffffffffu, s2, o);
        }
        float mu = s * (1.f / 512.f);
        float var = s2 * (1.f / 512.f) - mu * mu;
        float rstd = rsqrtf(var + 1e-5f);
#pragma unroll
        for (int j = 0; j < 16; j++) {
            int col = lane + j * 32;
            float v = H[row * 512 + col];
            float g = (v - mu) * rstd * gms[col] + bts[col];
            H[row * 512 + col] = fmaxf(g, 0.f);
        }
    }
    __syncthreads();

    // ---- class-segment reduce (rows are label-sorted) + atomic to global ----
    {
        int col = tid;  // 512 threads == 512 cols
        float sum = 0.f;
        int cur = clss[0];
#pragma unroll 4
        for (int r = 0; r < ROWS; r++) {
            int c2 = clss[r];
            if (c2 != cur) {
                atomicAdd(&Sl[(size_t)cur * DD + col], sum);
                sum = 0.f; cur = c2;
            }
            sum += H[r * 512 + col];
        }
        atomicAdd(&Sl[(size_t)cur * DD + col], sum);
    }
}

// ---------------- finalize: out = sum_l w_l * ((S_l/cnt) @ W2_l) + [cnt>0]*sum_l w_l*b2_l
// tile: 16 classes x 512 cols, K=512, 3 levels folded (w_l/cnt folded into A)
#define FIN_SMEM_BYTES (size_t)((512 + 16384) * 4)

__global__ __launch_bounds__(512, 1)
void finalize_kernel(const float* __restrict__ W2, const float* __restrict__ b2,
                     const float* __restrict__ temps, float* __restrict__ out)
{
    extern __shared__ float sm[];
    float* As = sm;         // [16][32]
    float* Bs = sm + 512;   // [32][512]
    const int tid = threadIdx.x;
    const int row0 = blockIdx.x * 16;
    const int c_t = tid & 63, r_t = tid >> 6;

    float t0 = temps[0], t1 = temps[1], t2 = temps[2];
    float mx = fmaxf(t0, fmaxf(t1, t2));
    float e0 = expf(t0 - mx), e1 = expf(t1 - mx), e2 = expf(t2 - mx);
    float inv = 1.f / (e0 + e1 + e2);
    float w[3] = {e0 * inv, e1 * inv, e2 * inv};

    unsigned long long acc[2][4];
#pragma unroll
    for (int i = 0; i < 2; i++)
#pragma unroll
        for (int j = 0; j < 4; j++) acc[i][j] = 0ULL;

    for (int l = 0; l < LL; l++) {
        for (int ch = 0; ch < NCHUNK; ch++) {
            __syncthreads();
            {
                int row = tid >> 5, kk = tid & 31;
                int cl = row0 + row;
                float cnt = fmaxf((float)g_counts[cl], 1.f);
                As[row * 32 + kk] =
                    g_S[(size_t)l * CC * DD + (size_t)cl * DD + ch * KB + kk] * (w[l] / cnt);
            }
#pragma unroll
            for (int i = 0; i < 8; i++) {
                int idx = tid + i * 512;
                int k = idx >> 7, c4 = (idx & 127) << 2;
                *(float4*)(Bs + k * 512 + c4) =
                    *(const float4*)(W2 + (size_t)l * DD * DD + (size_t)(ch * KB + k) * DD + c4);
            }
            __syncthreads();
#pragma unroll 8
            for (int k = 0; k < KB; k++) {
                ulonglong2 bA = *(const ulonglong2*)(Bs + k * 512 + (c_t << 2));
                ulonglong2 bB = *(const ulonglong2*)(Bs + k * 512 + 256 + (c_t << 2));
#pragma unroll
                for (int i = 0; i < 2; i++) {
                    float a = As[(r_t * 2 + i) * 32 + k];
                    unsigned long long ap = pack2(a, a);
                    acc[i][0] = fma2(ap, bA.x, acc[i][0]);
                    acc[i][1] = fma2(ap, bA.y, acc[i][1]);
                    acc[i][2] = fma2(ap, bB.x, acc[i][2]);
                    acc[i][3] = fma2(ap, bB.y, acc[i][3]);
                }
            }
        }
    }

    const int c0 = c_t << 2;
#pragma unroll
    for (int i = 0; i < 2; i++) {
        int cl = row0 + r_t * 2 + i;
        float has = (g_counts[cl] > 0) ? 1.f : 0.f;
        float2 p0 = unpack2(acc[i][0]), p1 = unpack2(acc[i][1]);
        float2 p2 = unpack2(acc[i][2]), p3 = unpack2(acc[i][3]);
        float4 v0, v1;
        v0.x = p0.x + has * (w[0] * b2[c0]       + w[1] * b2[DD + c0]       + w[2] * b2[2 * DD + c0]);
        v0.y = p0.y + has * (w[0] * b2[c0 + 1]   + w[1] * b2[DD + c0 + 1]   + w[2] * b2[2 * DD + c0 + 1]);
        v0.z = p1.x + has * (w[0] * b2[c0 + 2]   + w[1] * b2[DD + c0 + 2]   + w[2] * b2[2 * DD + c0 + 2]);
        v0.w = p1.y + has * (w[0] * b2[c0 + 3]   + w[1] * b2[DD + c0 + 3]   + w[2] * b2[2 * DD + c0 + 3]);
        int c1 = 256 + c0;
        v1.x = p2.x + has * (w[0] * b2[c1]       + w[1] * b2[DD + c1]       + w[2] * b2[2 * DD + c1]);
        v1.y = p2.y + has * (w[0] * b2[c1 + 1]   + w[1] * b2[DD + c1 + 1]   + w[2] * b2[2 * DD + c1 + 1]);
        v1.z = p3.x + has * (w[0] * b2[c1 + 2]   + w[1] * b2[DD + c1 + 2]   + w[2] * b2[2 * DD + c1 + 2]);
        v1.w = p3.y + has * (w[0] * b2[c1 + 3]   + w[1] * b2[DD + c1 + 3]   + w[2] * b2[2 * DD + c1 + 3]);
        *(float4*)(out + (size_t)cl * DD + c0) = v0;
        *(float4*)(out + (size_t)cl * DD + c1) = v1;
    }
}

// ---------------- launch ----------------
extern "C" void kernel_launch(void* const* d_in, const int* in_sizes, int n_in,
                              void* d_out, int out_size)
{
    const float* X      = (const float*)d_in[0];
    const int*   labels = (const int*)d_in[1];
    const float* W1     = (const float*)d_in[2];
    const float* b1     = (const float*)d_in[3];
    const float* gamma  = (const float*)d_in[4];
    const float* beta   = (const float*)d_in[5];
    const float* W2     = (const float*)d_in[6];
    const float* b2     = (const float*)d_in[7];
    const float* temps  = (const float*)d_in[8];
    float* out = (float*)d_out;

    cudaFuncSetAttribute(level_kernel, cudaFuncAttributeMaxDynamicSharedMemorySize,
                         (int)LVL_SMEM_BYTES);
    cudaFuncSetAttribute(finalize_kernel, cudaFuncAttributeMaxDynamicSharedMemorySize,
                         (int)FIN_SMEM_BYTES);

    zero_kernel<<<(LL * CC * DD + 255) / 256, 256>>>();
    hist_kernel<<<(NSUP + 255) / 256, 256>>>(labels);
    scan_kernel<<<1, CC>>>();
    scatter_kernel<<<NSUP / 8, 256>>>(X, labels);
    level_kernel<<<dim3(NSUP / ROWS, LL), 512, LVL_SMEM_BYTES>>>(W1, b1, gamma, beta);
    finalize_kernel<<<CC / 16, 512, FIN_SMEM_BYTES>>>(W2, b2, temps, out);
}

// round 5
// speedup vs baseline: 2.1466x; 2.1466x over previous
#include <cuda_runtime.h>
#include <cuda_fp16.h>
#include <cstdint>

#define NSUP 131072
#define DD   512
#define CC   1024
#define LL   3
#define MTILE 64
#define NCHUNK 16

// ---------------- device scratch ----------------
__device__ __half g_Xp[(size_t)NSUP * 1024];     // sorted X*64: [row][chunk16][hi32|lo32]
__device__ __half g_Bp[(size_t)LL * DD * 1024];  // W1^T*64:    [l][n][chunk16][hi32|lo32]
__device__ int   g_cls[NSUP];
__device__ int   g_counts[CC];
__device__ int   g_cursor[CC];
__device__ int   g_off[CC];
__device__ float g_S[LL * CC * DD];

// ---------------- helpers ----------------
__device__ __forceinline__ uint32_t smem_u32(const void* p) {
    uint32_t a;
    asm("{ .reg .u64 t; cvta.to.shared.u64 t, %1; cvt.u32.u64 %0, t; }" : "=r"(a) : "l"(p));
    return a;
}
__device__ __forceinline__ void cp_async16(void* sdst, const void* gsrc) {
    unsigned s = (unsigned)__cvta_generic_to_shared(sdst);
    asm volatile("cp.async.cg.shared.global [%0], [%1], 16;" :: "r"(s), "l"(gsrc));
}
__device__ __forceinline__ void cp_commit() { asm volatile("cp.async.commit_group;"); }
__device__ __forceinline__ void cp_wait1()  { asm volatile("cp.async.wait_group 1;"); }
__device__ __forceinline__ void cp_wait0()  { asm volatile("cp.async.wait_group 0;"); }

__device__ __forceinline__ void ldsm4(uint32_t* r, uint32_t addr) {
    asm volatile("ldmatrix.sync.aligned.m8n8.x4.shared.b16 {%0,%1,%2,%3}, [%4];"
                 : "=r"(r[0]), "=r"(r[1]), "=r"(r[2]), "=r"(r[3]) : "r"(addr));
}
__device__ __forceinline__ void mma16816(float* c, const uint32_t* a, uint32_t b0, uint32_t b1) {
    asm volatile(
        "mma.sync.aligned.m16n8k16.row.col.f32.f16.f16.f32 "
        "{%0,%1,%2,%3}, {%4,%5,%6,%7}, {%8,%9}, {%0,%1,%2,%3};"
        : "+f"(c[0]), "+f"(c[1]), "+f"(c[2]), "+f"(c[3])
        : "r"(a[0]), "r"(a[1]), "r"(a[2]), "r"(a[3]), "r"(b0), "r"(b1));
}

// ---------------- small kernels ----------------
__global__ void zero_kernel() {
    int i = blockIdx.x * 256 + threadIdx.x;
    if (i < LL * CC * DD) g_S[i] = 0.f;
    if (i < CC) { g_counts[i] = 0; g_cursor[i] = 0; }
}
__global__ void hist_kernel(const int* __restrict__ labels) {
    int i = blockIdx.x * 256 + threadIdx.x;
    if (i < NSUP) atomicAdd(&g_counts[labels[i]], 1);
}
__global__ void scan_kernel() {
    __shared__ int tmp[CC];
    int t = threadIdx.x;
    int v = g_counts[t];
    tmp[t] = v;
    __syncthreads();
    for (int o = 1; o < CC; o <<= 1) {
        int add = (t >= o) ? tmp[t - o] : 0;
        __syncthreads();
        tmp[t] += add;
        __syncthreads();
    }
    g_off[t] = tmp[t] - v;
}

// W1[l][k][n]*64 -> g_Bp[(l*512+n)*16 + k/32][k%32 hi | +32 lo]
__global__ void bprep_kernel(const float* __restrict__ W1) {
    int idx = blockIdx.x * 256 + threadIdx.x;
    if (idx >= LL * DD * DD) return;
    int l = idx >> 18;
    int rem = idx & ((1 << 18) - 1);
    int k = rem >> 9, n = rem & 511;
    float x = W1[idx] * 64.f;
    __half hi = __float2half_rn(x);
    __half lo = __float2half_rn(x - __half2float(hi));
    size_t o = ((size_t)(l * DD + n) * 16 + (k >> 5)) * 64 + (k & 31);
    g_Bp[o] = hi;
    g_Bp[o + 32] = lo;
}

// one warp per row: class-sorted scatter, X*64 fp16 hi/lo split
__global__ void scatter_kernel(const float* __restrict__ X, const int* __restrict__ labels) {
    int row  = blockIdx.x * 8 + (threadIdx.x >> 5);
    int lane = threadIdx.x & 31;
    int c = labels[row];
    int pos = 0;
    if (lane == 0) pos = g_off[c] + atomicAdd(&g_cursor[c], 1);
    pos = __shfl_sync(0xffffffffu, pos, 0);
    if (lane == 0) g_cls[pos] = c;
    const float* src = X + (size_t)row * DD;
    __half* dst = g_Xp + (size_t)pos * 1024;
#pragma unroll
    for (int i = 0; i < 16; i++) {
        float x = src[i * 32 + lane] * 64.f;
        __half hi = __float2half_rn(x);
        __half lo = __float2half_rn(x - __half2float(hi));
        dst[i * 64 + lane] = hi;
        dst[i * 64 + 32 + lane] = lo;
    }
}

// ---------------- fused mma.sync level kernel ----------------
// smem (1024-aligned): A 2x8192 | B 2x65536 (H[64][512] overlays B) | b1 | gamma | beta | cls
#define OFF_A   0
#define OFF_B   16384
#define OFF_B1  147456
#define OFF_G   149504
#define OFF_BT  151552
#define OFF_CL  153600
#define LVL_SMEM_BYTES (153856 + 1024)

__device__ __forceinline__ void load_chunk(char* Ad, char* Bd, const __half* Bp,
                                           int row0, int ch, int tid) {
    {   // A: 64 rows x 128B = 512 x 16B, one per thread
        int r = tid >> 3, b = (tid & 7) * 16;
        uint32_t sw = (uint32_t)(r * 128) + (uint32_t)(b ^ ((r & 7) << 4));
        cp_async16(Ad + sw, (const char*)g_Xp + (((size_t)(row0 + r) * 16 + ch) * 128 + b));
    }
#pragma unroll
    for (int i = 0; i < 8; i++) {   // B: 512 rows x 128B = 4096 x 16B
        int o = tid + 512 * i;
        int n = o >> 3, b = (o & 7) * 16;
        uint32_t sw = (uint32_t)(n * 128) + (uint32_t)(b ^ ((n & 7) << 4));
        cp_async16(Bd + sw, (const char*)Bp + (((size_t)n * 16 + ch) * 128 + b));
    }
    cp_commit();
}

__global__ __launch_bounds__(512, 1)
void level_kernel(const float* __restrict__ b1, const float* __restrict__ gamma,
                  const float* __restrict__ beta)
{
    extern __shared__ char raw[];
    char* sm = (char*)(((uintptr_t)raw + 1023) & ~(uintptr_t)1023);
    const int l = blockIdx.y;
    const int row0 = blockIdx.x * MTILE;
    const int tid = threadIdx.x;
    const int wid = tid >> 5, lane = tid & 31;
    const int wm = wid >> 3, wn = wid & 7;        // 2 x 8 warp grid: 32 rows x 64 cols
    const uint32_t sbase = smem_u32(sm);

    float* b1s = (float*)(sm + OFF_B1);
    float* gms = (float*)(sm + OFF_G);
    float* bts = (float*)(sm + OFF_BT);
    int*   clss = (int*)(sm + OFF_CL);

    if (tid < 512) {
        b1s[tid] = b1[l * DD + tid];
        gms[tid] = gamma[l * DD + tid];
        bts[tid] = beta[l * DD + tid];
    }
    if (tid < MTILE) clss[tid] = g_cls[row0 + tid];

    const __half* Bp = g_Bp + (size_t)l * DD * 1024;

    load_chunk(sm + OFF_A, sm + OFF_B, Bp, row0, 0, tid);
    load_chunk(sm + OFF_A + 8192, sm + OFF_B + 65536, Bp, row0, 1, tid);

    // per-thread fragment address components
    int arow0 = wm * 32 + (lane & 15);            // mf adds +16
    uint32_t art[2], axr[2];
#pragma unroll
    for (int mf = 0; mf < 2; mf++) {
        int r = arow0 + mf * 16;
        art[mf] = (uint32_t)(r * 128);
        axr[mf] = (uint32_t)((r & 7) << 4);
    }
    const uint32_t a_ts = (uint32_t)((lane >> 4) * 16);
    int bn = (lane & 7) + ((lane >> 4) & 1) * 8;  // nf2 adds +16
    const uint32_t b_kh = (uint32_t)(((lane >> 3) & 1) * 16);
    uint32_t brt[4], bxr[4];
#pragma unroll
    for (int nf2 = 0; nf2 < 4; nf2++) {
        int n = wn * 64 + nf2 * 16 + bn;
        brt[nf2] = (uint32_t)(n * 128);
        bxr[nf2] = (uint32_t)((n & 7) << 4);
    }

    float acc[2][8][4];
#pragma unroll
    for (int i = 0; i < 2; i++)
#pragma unroll
        for (int j = 0; j < 8; j++)
#pragma unroll
            for (int q = 0; q < 4; q++) acc[i][j][q] = 0.f;

    for (int ch = 0; ch < NCHUNK; ch++) {
        const int st = ch & 1;
        if (ch == NCHUNK - 1) cp_wait0(); else cp_wait1();
        __syncthreads();
        const uint32_t Ab = sbase + OFF_A + st * 8192;
        const uint32_t Bb = sbase + OFF_B + st * 65536;
#pragma unroll
        for (int ks = 0; ks < 2; ks++) {
            const uint32_t koff = ks * 32;
            uint32_t ahi[2][4], alo[2][4];
#pragma unroll
            for (int mf = 0; mf < 2; mf++) {
                ldsm4(ahi[mf], Ab + art[mf] + ((koff + a_ts)      ^ axr[mf]));
                ldsm4(alo[mf], Ab + art[mf] + ((koff + a_ts + 64) ^ axr[mf]));
            }
#pragma unroll
            for (int nf2 = 0; nf2 < 4; nf2++) {
                uint32_t bh[4], bl[4];
                ldsm4(bh, Bb + brt[nf2] + ((koff + b_kh)      ^ bxr[nf2]));
                ldsm4(bl, Bb + brt[nf2] + ((koff + b_kh + 64) ^ bxr[nf2]));
#pragma unroll
                for (int mf = 0; mf < 2; mf++) {
                    float* c0 = acc[mf][nf2 * 2];
                    float* c1 = acc[mf][nf2 * 2 + 1];
                    mma16816(c0, ahi[mf], bh[0], bh[1]);
                    mma16816(c1, ahi[mf], bh[2], bh[3]);
                    mma16816(c0, alo[mf], bh[0], bh[1]);
                    mma16816(c1, alo[mf], bh[2], bh[3]);
                    mma16816(c0, ahi[mf], bl[0], bl[1]);
                    mma16816(c1, ahi[mf], bl[2], bl[3]);
                }
            }
        }
        __syncthreads();
        if (ch + 2 < NCHUNK)
            load_chunk(sm + OFF_A + st * 8192, sm + OFF_B + st * 65536, Bp, row0, ch + 2, tid);
    }
    __syncthreads();

    // ---- write H = acc/4096 into smem (overlay B region) ----
    float* H = (float*)(sm + OFF_B);
    const float inv = 1.f / 4096.f;
    {
        const int rb = wm * 32 + (lane >> 2);
        const int cb = wn * 64 + (lane & 3) * 2;
#pragma unroll
        for (int mf = 0; mf < 2; mf++)
#pragma unroll
            for (int nf = 0; nf < 8; nf++) {
                int r = rb + mf * 16, c = cb + nf * 8;
                H[r * 512 + c]           = acc[mf][nf][0] * inv;
                H[r * 512 + c + 1]       = acc[mf][nf][1] * inv;
                H[(r + 8) * 512 + c]     = acc[mf][nf][2] * inv;
                H[(r + 8) * 512 + c + 1] = acc[mf][nf][3] * inv;
            }
    }
    __syncthreads();

    // ---- LayerNorm + ReLU: warp w -> rows 4w..4w+3 (16 warps x 4 = 64) ----
#pragma unroll
    for (int rr = 0; rr < 4; rr++) {
        int row = wid * 4 + rr;
        float s = 0.f, s2 = 0.f;
#pragma unroll
        for (int j = 0; j < 16; j++) {
            int col = lane + j * 32;
            float v = H[row * 512 + col] + b1s[col];
            s += v; s2 += v * v;
        }
#pragma unroll
        for (int o = 16; o; o >>= 1) {
            s  += __shfl_xor_sync(0xffffffffu, s, o);
            s2 += __shfl_xor_sync(0xffffffffu, s2, o);
        }
        float mu = s * (1.f / 512.f);
        float var = s2 * (1.f / 512.f) - mu * mu;
        float rstd = rsqrtf(var + 1e-5f);
#pragma unroll
        for (int j = 0; j < 16; j++) {
            int col = lane + j * 32;
            float v = H[row * 512 + col] + b1s[col];
            float g = (v - mu) * rstd * gms[col] + bts[col];
            H[row * 512 + col] = fmaxf(g, 0.f);
        }
    }
    __syncthreads();

    // ---- class-segment reduce (rows label-sorted) + atomic to global ----
    {
        float* Sl = g_S + (size_t)l * CC * DD;
        int col = tid;  // 512 threads == 512 cols
        float sum = 0.f;
        int cur = clss[0];
#pragma unroll 4
        for (int r = 0; r < MTILE; r++) {
            int c2 = clss[r];
            if (c2 != cur) {
                atomicAdd(&Sl[(size_t)cur * DD + col], sum);
                sum = 0.f; cur = c2;
            }
            sum += H[r * 512 + col];
        }
        atomicAdd(&Sl[(size_t)cur * DD + col], sum);
    }
}

// ---------------- finalize: out = sum_l w_l*((S_l/cnt)@W2_l) + [cnt>0]*sum_l w_l*b2_l
#define FIN_SMEM_BYTES ((512 + 16384) * 4)

__global__ __launch_bounds__(512, 1)
void finalize_kernel(const float* __restrict__ W2, const float* __restrict__ b2,
                     const float* __restrict__ temps, float* __restrict__ out)
{
    extern __shared__ float smf[];
    float* As = smf;          // [16][32]
    float* Bs = smf + 512;    // [32][512]
    const int tid = threadIdx.x;
    const int row0 = blockIdx.x * 16;
    const int c_t = tid & 63, r_t = tid >> 6;

    float t0 = temps[0], t1 = temps[1], t2 = temps[2];
    float mx = fmaxf(t0, fmaxf(t1, t2));
    float e0 = expf(t0 - mx), e1 = expf(t1 - mx), e2 = expf(t2 - mx);
    float inv = 1.f / (e0 + e1 + e2);
    float w[3] = {e0 * inv, e1 * inv, e2 * inv};

    float acc[2][8];
#pragma unroll
    for (int i = 0; i < 2; i++)
#pragma unroll
        for (int j = 0; j < 8; j++) acc[i][j] = 0.f;

    const int c0 = c_t << 2;
    for (int l = 0; l < LL; l++) {
        for (int ch = 0; ch < NCHUNK; ch++) {
            __syncthreads();
            {
                int row = tid >> 5, kk = tid & 31;
                int cl = row0 + row;
                float cnt = fmaxf((float)g_counts[cl], 1.f);
                As[row * 32 + kk] =
                    g_S[(size_t)l * CC * DD + (size_t)cl * DD + ch * 32 + kk] * (w[l] / cnt);
            }
#pragma unroll
            for (int i = 0; i < 8; i++) {
                int idx = tid + i * 512;
                int k = idx >> 7, c4 = (idx & 127) << 2;
                *(float4*)(Bs + k * 512 + c4) =
                    *(const float4*)(W2 + (size_t)l * DD * DD + (size_t)(ch * 32 + k) * DD + c4);
            }
            __syncthreads();
#pragma unroll 4
            for (int k = 0; k < 32; k++) {
                float4 bA = *(const float4*)(Bs + k * 512 + c0);
                float4 bB = *(const float4*)(Bs + k * 512 + 256 + c0);
#pragma unroll
                for (int i = 0; i < 2; i++) {
                    float a = As[(r_t * 2 + i) * 32 + k];
                    acc[i][0] += a * bA.x; acc[i][1] += a * bA.y;
                    acc[i][2] += a * bA.z; acc[i][3] += a * bA.w;
                    acc[i][4] += a * bB.x; acc[i][5] += a * bB.y;
                    acc[i][6] += a * bB.z; acc[i][7] += a * bB.w;
                }
            }
        }
    }

#pragma unroll
    for (int i = 0; i < 2; i++) {
        int cl = row0 + r_t * 2 + i;
        float has = (g_counts[cl] > 0) ? 1.f : 0.f;
        float4 v0, v1;
        v0.x = acc[i][0] + has * (w[0] * b2[c0]     + w[1] * b2[DD + c0]     + w[2] * b2[2 * DD + c0]);
        v0.y = acc[i][1] + has * (w[0] * b2[c0 + 1] + w[1] * b2[DD + c0 + 1] + w[2] * b2[2 * DD + c0 + 1]);
        v0.z = acc[i][2] + has * (w[0] * b2[c0 + 2] + w[1] * b2[DD + c0 + 2] + w[2] * b2[2 * DD + c0 + 2]);
        v0.w = acc[i][3] + has * (w[0] * b2[c0 + 3] + w[1] * b2[DD + c0 + 3] + w[2] * b2[2 * DD + c0 + 3]);
        int c1 = 256 + c0;
        v1.x = acc[i][4] + has * (w[0] * b2[c1]     + w[1] * b2[DD + c1]     + w[2] * b2[2 * DD + c1]);
        v1.y = acc[i][5] + has * (w[0] * b2[c1 + 1] + w[1] * b2[DD + c1 + 1] + w[2] * b2[2 * DD + c1 + 1]);
        v1.z = acc[i][6] + has * (w[0] * b2[c1 + 2] + w[1] * b2[DD + c1 + 2] + w[2] * b2[2 * DD + c1 + 2]);
        v1.w = acc[i][7] + has * (w[0] * b2[c1 + 3] + w[1] * b2[DD + c1 + 3] + w[2] * b2[2 * DD + c1 + 3]);
        *(float4*)(out + (size_t)cl * DD + c0) = v0;
        *(float4*)(out + (size_t)cl * DD + c1) = v1;
    }
}

// ---------------- launch ----------------
extern "C" void kernel_launch(void* const* d_in, const int* in_sizes, int n_in,
                              void* d_out, int out_size)
{
    const float* X      = (const float*)d_in[0];
    const int*   labels = (const int*)d_in[1];
    const float* W1     = (const float*)d_in[2];
    const float* b1     = (const float*)d_in[3];
    const float* gamma  = (const float*)d_in[4];
    const float* beta   = (const float*)d_in[5];
    const float* W2     = (const float*)d_in[6];
    const float* b2     = (const float*)d_in[7];
    const float* temps  = (const float*)d_in[8];
    float* out = (float*)d_out;

    cudaFuncSetAttribute(level_kernel, cudaFuncAttributeMaxDynamicSharedMemorySize,
                         LVL_SMEM_BYTES);
    cudaFuncSetAttribute(finalize_kernel, cudaFuncAttributeMaxDynamicSharedMemorySize,
                         FIN_SMEM_BYTES);

    zero_kernel<<<(LL * CC * DD + 255) / 256, 256>>>();
    hist_kernel<<<(NSUP + 255) / 256, 256>>>(labels);
    scan_kernel<<<1, CC>>>();
    scatter_kernel<<<NSUP / 8, 256>>>(X, labels);
    bprep_kernel<<<(LL * DD * DD + 255) / 256, 256>>>(W1);
    level_kernel<<<dim3(NSUP / MTILE, LL), 512, LVL_SMEM_BYTES>>>(b1, gamma, beta);
    finalize_kernel<<<CC / 16, 512, FIN_SMEM_BYTES>>>(W2, b2, temps, out);
}

// round 6
// speedup vs baseline: 3.8459x; 1.7916x over previous
#include <cuda_runtime.h>
#include <cuda_fp16.h>
#include <cstdint>

#define NSUP 131072
#define DD   512
#define CC   1024
#define LL   3
#define MTILE 64
#define NCH  8          // K chunks of 64

// ---------------- device scratch ----------------
__device__ __half g_Xh[(size_t)NSUP * DD];      // sorted X, fp16, contiguous [row][k]
__device__ __half g_Bh[(size_t)LL * DD * DD];   // W1^T fp16: [l][n][k]
__device__ int   g_cls[NSUP];
__device__ int   g_counts[CC];
__device__ int   g_cursor[CC];
__device__ int   g_off[CC];
__device__ float g_S[LL * CC * DD];

// ---------------- helpers ----------------
__device__ __forceinline__ uint32_t smem_u32(const void* p) {
    uint32_t a;
    asm("{ .reg .u64 t; cvta.to.shared.u64 t, %1; cvt.u32.u64 %0, t; }" : "=r"(a) : "l"(p));
    return a;
}
__device__ __forceinline__ void cp_async16(void* sdst, const void* gsrc) {
    unsigned s = (unsigned)__cvta_generic_to_shared(sdst);
    asm volatile("cp.async.cg.shared.global [%0], [%1], 16;" :: "r"(s), "l"(gsrc));
}
__device__ __forceinline__ void cp_commit() { asm volatile("cp.async.commit_group;"); }
__device__ __forceinline__ void cp_wait1()  { asm volatile("cp.async.wait_group 1;"); }
__device__ __forceinline__ void cp_wait0()  { asm volatile("cp.async.wait_group 0;"); }

__device__ __forceinline__ void ldsm4(uint32_t* r, uint32_t addr) {
    asm volatile("ldmatrix.sync.aligned.m8n8.x4.shared.b16 {%0,%1,%2,%3}, [%4];"
                 : "=r"(r[0]), "=r"(r[1]), "=r"(r[2]), "=r"(r[3]) : "r"(addr));
}
__device__ __forceinline__ void mma16816(float* c, const uint32_t* a, uint32_t b0, uint32_t b1) {
    asm volatile(
        "mma.sync.aligned.m16n8k16.row.col.f32.f16.f16.f32 "
        "{%0,%1,%2,%3}, {%4,%5,%6,%7}, {%8,%9}, {%0,%1,%2,%3};"
        : "+f"(c[0]), "+f"(c[1]), "+f"(c[2]), "+f"(c[3])
        : "r"(a[0]), "r"(a[1]), "r"(a[2]), "r"(a[3]), "r"(b0), "r"(b1));
}

// ---------------- small kernels ----------------
__global__ void zero_kernel() {
    int i = blockIdx.x * 256 + threadIdx.x;
    if (i < LL * CC * DD) g_S[i] = 0.f;
    if (i < CC) { g_counts[i] = 0; g_cursor[i] = 0; }
}
__global__ void hist_kernel(const int* __restrict__ labels) {
    int i = blockIdx.x * 256 + threadIdx.x;
    if (i < NSUP) atomicAdd(&g_counts[labels[i]], 1);
}
__global__ void scan_kernel() {
    __shared__ int tmp[CC];
    int t = threadIdx.x;
    int v = g_counts[t];
    tmp[t] = v;
    __syncthreads();
    for (int o = 1; o < CC; o <<= 1) {
        int add = (t >= o) ? tmp[t - o] : 0;
        __syncthreads();
        tmp[t] += add;
        __syncthreads();
    }
    g_off[t] = tmp[t] - v;
}

// W1[l][k][n] -> g_Bh[l][n][k] fp16
__global__ void bprep_kernel(const float* __restrict__ W1) {
    int idx = blockIdx.x * 256 + threadIdx.x;
    if (idx >= LL * DD * DD) return;
    int l = idx >> 18;
    int rem = idx & ((1 << 18) - 1);
    int k = rem >> 9, n = rem & 511;
    g_Bh[((size_t)(l * DD + n) << 9) + k] = __float2half_rn(W1[idx]);
}

// one warp per row: class-sorted scatter to fp16
__global__ void scatter_kernel(const float* __restrict__ X, const int* __restrict__ labels) {
    int row  = blockIdx.x * 8 + (threadIdx.x >> 5);
    int lane = threadIdx.x & 31;
    int c = labels[row];
    int pos = 0;
    if (lane == 0) pos = g_off[c] + atomicAdd(&g_cursor[c], 1);
    pos = __shfl_sync(0xffffffffu, pos, 0);
    if (lane == 0) g_cls[pos] = c;
    const float2* src = (const float2*)(X + (size_t)row * DD);
    __half2* dst = (__half2*)(g_Xh + (size_t)pos * DD);
#pragma unroll
    for (int i = 0; i < 8; i++) {
        float2 v = src[i * 32 + lane];
        dst[i * 32 + lane] = __floats2half2_rn(v.x, v.y);
    }
}

// ---------------- fused mma.sync level kernel (single fp16 pass) ----------------
// smem (1024-aligned): A 2x8192 | B 2x65536 (H[64][512] f32 overlays B) | b1 | gamma | beta | cls
#define OFF_A   0
#define OFF_B   16384
#define OFF_B1  147456
#define OFF_G   149504
#define OFF_BT  151552
#define OFF_CL  153600
#define LVL_SMEM_BYTES (153856 + 1024)

__device__ __forceinline__ void load_chunk(char* Ad, char* Bd, const __half* Bp,
                                           int row0, int ch, int tid) {
    {   // A: 64 rows x 128B (k64) = 512 x 16B, one per thread
        int r = tid >> 3, b = (tid & 7) * 16;
        uint32_t sw = (uint32_t)(r * 128) + (uint32_t)(b ^ ((r & 7) << 4));
        cp_async16(Ad + sw, (const char*)g_Xh + ((size_t)(row0 + r) * 1024 + ch * 128 + b));
    }
#pragma unroll
    for (int i = 0; i < 8; i++) {   // B: 512 n-rows x 128B = 4096 x 16B
        int o = tid + 512 * i;
        int n = o >> 3, b = (o & 7) * 16;
        uint32_t sw = (uint32_t)(n * 128) + (uint32_t)(b ^ ((n & 7) << 4));
        cp_async16(Bd + sw, (const char*)Bp + ((size_t)n * 1024 + ch * 128 + b));
    }
    cp_commit();
}

__global__ __launch_bounds__(512, 1)
void level_kernel(const float* __restrict__ b1, const float* __restrict__ gamma,
                  const float* __restrict__ beta)
{
    extern __shared__ char raw[];
    char* sm = (char*)(((uintptr_t)raw + 1023) & ~(uintptr_t)1023);
    const int l = blockIdx.y;
    const int row0 = blockIdx.x * MTILE;
    const int tid = threadIdx.x;
    const int wid = tid >> 5, lane = tid & 31;
    const int wm = wid >> 3, wn = wid & 7;        // 2 x 8 warp grid: 32 rows x 64 cols
    const uint32_t sbase = smem_u32(sm);

    float* b1s = (float*)(sm + OFF_B1);
    float* gms = (float*)(sm + OFF_G);
    float* bts = (float*)(sm + OFF_BT);
    int*   clss = (int*)(sm + OFF_CL);

    b1s[tid] = b1[l * DD + tid];
    gms[tid] = gamma[l * DD + tid];
    bts[tid] = beta[l * DD + tid];
    if (tid < MTILE) clss[tid] = g_cls[row0 + tid];

    const __half* Bp = g_Bh + (size_t)l * DD * DD;

    load_chunk(sm + OFF_A, sm + OFF_B, Bp, row0, 0, tid);
    load_chunk(sm + OFF_A + 8192, sm + OFF_B + 65536, Bp, row0, 1, tid);

    // fragment address components (validated in R5)
    int arow0 = wm * 32 + (lane & 15);
    uint32_t art[2], axr[2];
#pragma unroll
    for (int mf = 0; mf < 2; mf++) {
        int r = arow0 + mf * 16;
        art[mf] = (uint32_t)(r * 128);
        axr[mf] = (uint32_t)((r & 7) << 4);
    }
    const uint32_t a_ts = (uint32_t)((lane >> 4) * 16);
    int bn = (lane & 7) + ((lane >> 4) & 1) * 8;
    const uint32_t b_kh = (uint32_t)(((lane >> 3) & 1) * 16);
    uint32_t brt[4], bxr[4];
#pragma unroll
    for (int nf2 = 0; nf2 < 4; nf2++) {
        int n = wn * 64 + nf2 * 16 + bn;
        brt[nf2] = (uint32_t)(n * 128);
        bxr[nf2] = (uint32_t)((n & 7) << 4);
    }

    float acc[2][8][4];
#pragma unroll
    for (int i = 0; i < 2; i++)
#pragma unroll
        for (int j = 0; j < 8; j++)
#pragma unroll
            for (int q = 0; q < 4; q++) acc[i][j][q] = 0.f;

    for (int ch = 0; ch < NCH; ch++) {
        const int st = ch & 1;
        if (ch == NCH - 1) cp_wait0(); else cp_wait1();
        __syncthreads();
        const uint32_t Ab = sbase + OFF_A + st * 8192;
        const uint32_t Bb = sbase + OFF_B + st * 65536;
#pragma unroll
        for (int ks = 0; ks < 4; ks++) {          // 4 x k16 inside the 128B row
            const uint32_t koff = ks * 32;
            uint32_t a[2][4];
#pragma unroll
            for (int mf = 0; mf < 2; mf++)
                ldsm4(a[mf], Ab + art[mf] + ((koff + a_ts) ^ axr[mf]));
#pragma unroll
            for (int nf2 = 0; nf2 < 4; nf2++) {
                uint32_t bh[4];
                ldsm4(bh, Bb + brt[nf2] + ((koff + b_kh) ^ bxr[nf2]));
#pragma unroll
                for (int mf = 0; mf < 2; mf++) {
                    mma16816(acc[mf][nf2 * 2],     a[mf], bh[0], bh[1]);
                    mma16816(acc[mf][nf2 * 2 + 1], a[mf], bh[2], bh[3]);
                }
            }
        }
        __syncthreads();
        if (ch + 2 < NCH)
            load_chunk(sm + OFF_A + st * 8192, sm + OFF_B + st * 65536, Bp, row0, ch + 2, tid);
    }
    __syncthreads();

    // ---- write H = acc into smem (overlay B region) ----
    float* H = (float*)(sm + OFF_B);
    {
        const int rb = wm * 32 + (lane >> 2);
        const int cb = wn * 64 + (lane & 3) * 2;
#pragma unroll
        for (int mf = 0; mf < 2; mf++)
#pragma unroll
            for (int nf = 0; nf < 8; nf++) {
                int r = rb + mf * 16, c = cb + nf * 8;
                H[r * 512 + c]           = acc[mf][nf][0];
                H[r * 512 + c + 1]       = acc[mf][nf][1];
                H[(r + 8) * 512 + c]     = acc[mf][nf][2];
                H[(r + 8) * 512 + c + 1] = acc[mf][nf][3];
            }
    }
    __syncthreads();

    // ---- LayerNorm + ReLU: warp w -> rows 4w..4w+3 ----
#pragma unroll
    for (int rr = 0; rr < 4; rr++) {
        int row = wid * 4 + rr;
        float s = 0.f, s2 = 0.f;
#pragma unroll
        for (int j = 0; j < 16; j++) {
            int col = lane + j * 32;
            float v = H[row * 512 + col] + b1s[col];
            s += v; s2 += v * v;
        }
#pragma unroll
        for (int o = 16; o; o >>= 1) {
            s  += __shfl_xor_sync(0xffffffffu, s, o);
            s2 += __shfl_xor_sync(0xffffffffu, s2, o);
        }
        float mu = s * (1.f / 512.f);
        float var = s2 * (1.f / 512.f) - mu * mu;
        float rstd = rsqrtf(var + 1e-5f);
#pragma unroll
        for (int j = 0; j < 16; j++) {
            int col = lane + j * 32;
            float v = H[row * 512 + col] + b1s[col];
            float g = (v - mu) * rstd * gms[col] + bts[col];
            H[row * 512 + col] = fmaxf(g, 0.f);
        }
    }
    __syncthreads();

    // ---- class-segment reduce (rows label-sorted) + atomic to global ----
    {
        float* Sl = g_S + (size_t)l * CC * DD;
        int col = tid;
        float sum = 0.f;
        int cur = clss[0];
#pragma unroll 4
        for (int r = 0; r < MTILE; r++) {
            int c2 = clss[r];
            if (c2 != cur) {
                atomicAdd(&Sl[(size_t)cur * DD + col], sum);
                sum = 0.f; cur = c2;
            }
            sum += H[r * 512 + col];
        }
        atomicAdd(&Sl[(size_t)cur * DD + col], sum);
    }
}

// ---------------- finalize: out = sum_l w_l*((S_l/cnt)@W2_l) + [cnt>0]*sum_l w_l*b2_l
#define FIN_SMEM_BYTES ((512 + 16384) * 4)

__global__ __launch_bounds__(512, 1)
void finalize_kernel(const float* __restrict__ W2, const float* __restrict__ b2,
                     const float* __restrict__ temps, float* __restrict__ out)
{
    extern __shared__ float smf[];
    float* As = smf;          // [16][32]
    float* Bs = smf + 512;    // [32][512]
    const int tid = threadIdx.x;
    const int row0 = blockIdx.x * 16;
    const int c_t = tid & 63, r_t = tid >> 6;

    float t0 = temps[0], t1 = temps[1], t2 = temps[2];
    float mx = fmaxf(t0, fmaxf(t1, t2));
    float e0 = expf(t0 - mx), e1 = expf(t1 - mx), e2 = expf(t2 - mx);
    float inv = 1.f / (e0 + e1 + e2);
    float w[3] = {e0 * inv, e1 * inv, e2 * inv};

    float acc[2][8];
#pragma unroll
    for (int i = 0; i < 2; i++)
#pragma unroll
        for (int j = 0; j < 8; j++) acc[i][j] = 0.f;

    const int c0 = c_t << 2;
    for (int l = 0; l < LL; l++) {
        for (int ch = 0; ch < 16; ch++) {
            __syncthreads();
            {
                int row = tid >> 5, kk = tid & 31;
                int cl = row0 + row;
                float cnt = fmaxf((float)g_counts[cl], 1.f);
                As[row * 32 + kk] =
                    g_S[(size_t)l * CC * DD + (size_t)cl * DD + ch * 32 + kk] * (w[l] / cnt);
            }
#pragma unroll
            for (int i = 0; i < 8; i++) {
                int idx = tid + i * 512;
                int k = idx >> 7, c4 = (idx & 127) << 2;
                *(float4*)(Bs + k * 512 + c4) =
                    *(const float4*)(W2 + (size_t)l * DD * DD + (size_t)(ch * 32 + k) * DD + c4);
            }
            __syncthreads();
#pragma unroll 4
            for (int k = 0; k < 32; k++) {
                float4 bA = *(const float4*)(Bs + k * 512 + c0);
                float4 bB = *(const float4*)(Bs + k * 512 + 256 + c0);
#pragma unroll
                for (int i = 0; i < 2; i++) {
                    float a = As[(r_t * 2 + i) * 32 + k];
                    acc[i][0] += a * bA.x; acc[i][1] += a * bA.y;
                    acc[i][2] += a * bA.z; acc[i][3] += a * bA.w;
                    acc[i][4] += a * bB.x; acc[i][5] += a * bB.y;
                    acc[i][6] += a * bB.z; acc[i][7] += a * bB.w;
                }
            }
        }
    }

#pragma unroll
    for (int i = 0; i < 2; i++) {
        int cl = row0 + r_t * 2 + i;
        float has = (g_counts[cl] > 0) ? 1.f : 0.f;
        float4 v0, v1;
        v0.x = acc[i][0] + has * (w[0] * b2[c0]     + w[1] * b2[DD + c0]     + w[2] * b2[2 * DD + c0]);
        v0.y = acc[i][1] + has * (w[0] * b2[c0 + 1] + w[1] * b2[DD + c0 + 1] + w[2] * b2[2 * DD + c0 + 1]);
        v0.z = acc[i][2] + has * (w[0] * b2[c0 + 2] + w[1] * b2[DD + c0 + 2] + w[2] * b2[2 * DD + c0 + 2]);
        v0.w = acc[i][3] + has * (w[0] * b2[c0 + 3] + w[1] * b2[DD + c0 + 3] + w[2] * b2[2 * DD + c0 + 3]);
        int c1 = 256 + c0;
        v1.x = acc[i][4] + has * (w[0] * b2[c1]     + w[1] * b2[DD + c1]     + w[2] * b2[2 * DD + c1]);
        v1.y = acc[i][5] + has * (w[0] * b2[c1 + 1] + w[1] * b2[DD + c1 + 1] + w[2] * b2[2 * DD + c1 + 1]);
        v1.z = acc[i][6] + has * (w[0] * b2[c1 + 2] + w[1] * b2[DD + c1 + 2] + w[2] * b2[2 * DD + c1 + 2]);
        v1.w = acc[i][7] + has * (w[0] * b2[c1 + 3] + w[1] * b2[DD + c1 + 3] + w[2] * b2[2 * DD + c1 + 3]);
        *(float4*)(out + (size_t)cl * DD + c0) = v0;
        *(float4*)(out + (size_t)cl * DD + c1) = v1;
    }
}

// ---------------- launch ----------------
extern "C" void kernel_launch(void* const* d_in, const int* in_sizes, int n_in,
                              void* d_out, int out_size)
{
    const float* X      = (const float*)d_in[0];
    const int*   labels = (const int*)d_in[1];
    const float* W1     = (const float*)d_in[2];
    const float* b1     = (const float*)d_in[3];
    const float* gamma  = (const float*)d_in[4];
    const float* beta   = (const float*)d_in[5];
    const float* W2     = (const float*)d_in[6];
    const float* b2     = (const float*)d_in[7];
    const float* temps  = (const float*)d_in[8];
    float* out = (float*)d_out;

    cudaFuncSetAttribute(level_kernel, cudaFuncAttributeMaxDynamicSharedMemorySize,
                         LVL_SMEM_BYTES);
    cudaFuncSetAttribute(finalize_kernel, cudaFuncAttributeMaxDynamicSharedMemorySize,
                         FIN_SMEM_BYTES);

    zero_kernel<<<(LL * CC * DD + 255) / 256, 256>>>();
    hist_kernel<<<(NSUP + 255) / 256, 256>>>(labels);
    scan_kernel<<<1, CC>>>();
    scatter_kernel<<<NSUP / 8, 256>>>(X, labels);
    bprep_kernel<<<(LL * DD * DD + 255) / 256, 256>>>(W1);
    level_kernel<<<dim3(NSUP / MTILE, LL), 512, LVL_SMEM_BYTES>>>(b1, gamma, beta);
    finalize_kernel<<<CC / 16, 512, FIN_SMEM_BYTES>>>(W2, b2, temps, out);
}